// round 1
// baseline (speedup 1.0000x reference)
#include <cuda_runtime.h>
#include <math.h>

// ---------------------------------------------------------------------------
// GTN: H = diag(d1*d0) * HA * (HB * HB2)  with shared union sparsity pattern.
// y head computed only at target rows.
// Inputs (metadata order):
//  0 A      [5,2048,2048] f32
//  1 X      [2048,512]    f32
//  2 w0_1   [2,5]         f32
//  3 w0_2   [2,5]         f32
//  4 w1_1   [2,5]         f32
//  5 gcn_w  [128,512]     f32
//  6 gcn_b  [128]         f32
//  7 lin_w  [8,256]       f32
//  8 lin_b  [8]           f32
//  9 target_x [512]       i32
// Output (flattened tuple): y[512*8] | all_Ws[3*2*5] | H[2*2048*2048]
// ---------------------------------------------------------------------------

#define NN    2048
#define NE    5
#define NC    2
#define CAP   256      // max nnz per row of the union pattern (mean ~100)
#define NT    512      // number of targets
#define XD    512      // feature dim
#define WOUT  128      // gcn out dim
#define NCLS  8        // classes

#define Y_OFF  0
#define WS_OFF (NT * NCLS)            // 4096
#define H_OFF  (WS_OFF + 3 * NC * NE) // 4126

// ------------------------- static device scratch ---------------------------
__device__ int   g_cnt[NN];                 // nnz per row (union pattern)
__device__ int   g_cols[NN * CAP];          // column indices
__device__ float g_hav [NC][NN * CAP];      // HA values per channel
__device__ float g_hbv [NC][NN * CAP];      // HB values per channel
__device__ float g_hb2v[NC][NN * CAP];      // HB2 values per channel
__device__ float g_s[3][NC][NE];            // softmaxed weights
__device__ float g_rB  [NC][NN];            // rowsum(HB)
__device__ float g_rB2 [NC][NN];            // rowsum(HB2)
__device__ float g_rM  [NC][NN];            // rowsum(HB@HB2)
__device__ float g_deg0[NC][NN];
__device__ float g_scale[NC][NN];           // d1*d0 per row
__device__ float g_M[NC][NN][NN];           // HB @ HB2 dense (33.5 MB)
__device__ float g_gwT[XD][WOUT];           // gcn_w transposed

// ------------------------------ helpers ------------------------------------
__device__ __forceinline__ float warpSum(float v) {
    #pragma unroll
    for (int o = 16; o > 0; o >>= 1) v += __shfl_down_sync(0xffffffffu, v, o);
    return v;
}

// --------------------------- kernel 1: init --------------------------------
// zero row counters + compute the 3 softmaxes, write all_Ws to output.
__global__ void k_init(const float* __restrict__ w1, const float* __restrict__ w2,
                       const float* __restrict__ w3, float* __restrict__ out_ws) {
    int tid = threadIdx.x;
    for (int i = tid; i < NN; i += blockDim.x) g_cnt[i] = 0;
    if (tid < 3 * NC) {
        int m = tid / NC, c = tid % NC;
        const float* w = (m == 0 ? w1 : (m == 1 ? w2 : w3)) + c * NE;
        float mx = w[0];
        #pragma unroll
        for (int e = 1; e < NE; e++) mx = fmaxf(mx, w[e]);
        float ex[NE], s = 0.f;
        #pragma unroll
        for (int e = 0; e < NE; e++) { ex[e] = expf(w[e] - mx); s += ex[e]; }
        float inv = 1.f / s;
        #pragma unroll
        for (int e = 0; e < NE; e++) {
            float v = ex[e] * inv;
            g_s[m][c][e] = v;
            out_ws[m * NC * NE + c * NE + e] = v;
        }
    }
}

// ------------------- kernel 2: build sparse pattern + values ---------------
__global__ void k_fill(const float* __restrict__ A) {
    int i = blockIdx.x;
    // load softmax weights into registers
    float s1[NC][NE], s2[NC][NE], s3[NC][NE];
    #pragma unroll
    for (int c = 0; c < NC; c++)
        #pragma unroll
        for (int e = 0; e < NE; e++) {
            s1[c][e] = g_s[0][c][e]; s2[c][e] = g_s[1][c][e]; s3[c][e] = g_s[2][c][e];
        }
    for (int j = threadIdx.x; j < NN; j += blockDim.x) {
        float a[NE];
        bool nz = false;
        #pragma unroll
        for (int e = 0; e < NE; e++) {
            a[e] = A[(size_t)e * NN * NN + (size_t)i * NN + j];
            nz |= (a[e] != 0.f);
        }
        if (nz) {
            int slot = atomicAdd(&g_cnt[i], 1);
            if (slot < CAP) {
                int p = i * CAP + slot;
                g_cols[p] = j;
                #pragma unroll
                for (int c = 0; c < NC; c++) {
                    float va = 0.f, vb = 0.f, vb2 = 0.f;
                    #pragma unroll
                    for (int e = 0; e < NE; e++) {
                        va  += s1[c][e] * a[e];
                        vb  += s2[c][e] * a[e];
                        vb2 += s3[c][e] * a[e];
                    }
                    g_hav[c][p] = va; g_hbv[c][p] = vb; g_hb2v[c][p] = vb2;
                }
            }
        }
    }
}

// --------------- kernel 3: row sums of HB, HB2 (per channel) ---------------
__global__ void k_rowstats() {
    int r = blockIdx.x;
    int cnt = min(g_cnt[r], CAP);
    float a0 = 0, a1 = 0, b0 = 0, b1 = 0;
    for (int t = threadIdx.x; t < cnt; t += blockDim.x) {
        int p = r * CAP + t;
        a0 += g_hbv[0][p];  a1 += g_hbv[1][p];
        b0 += g_hb2v[0][p]; b1 += g_hb2v[1][p];
    }
    a0 = warpSum(a0); a1 = warpSum(a1); b0 = warpSum(b0); b1 = warpSum(b1);
    __shared__ float sh[4][4];
    int w = threadIdx.x >> 5, lane = threadIdx.x & 31;
    if (lane == 0) { sh[w][0] = a0; sh[w][1] = a1; sh[w][2] = b0; sh[w][3] = b1; }
    __syncthreads();
    if (threadIdx.x == 0) {
        float v0 = 0, v1 = 0, v2 = 0, v3 = 0;
        for (int k = 0; k < 4; k++) { v0 += sh[k][0]; v1 += sh[k][1]; v2 += sh[k][2]; v3 += sh[k][3]; }
        g_rB[0][r] = v0; g_rB[1][r] = v1; g_rB2[0][r] = v2; g_rB2[1][r] = v3;
    }
}

// ---- kernel 4: deg0[i] = Sum HA[i,k]*rB[k];  rM[i] = Sum HB[i,k]*rB2[k] ----
__global__ void k_deg() {
    int r = blockIdx.x;
    int cnt = min(g_cnt[r], CAP);
    float d0 = 0, d1 = 0, m0 = 0, m1 = 0;
    for (int t = threadIdx.x; t < cnt; t += blockDim.x) {
        int p = r * CAP + t;
        int col = g_cols[p];
        d0 += g_hav[0][p] * g_rB[0][col];
        d1 += g_hav[1][p] * g_rB[1][col];
        m0 += g_hbv[0][p] * g_rB2[0][col];
        m1 += g_hbv[1][p] * g_rB2[1][col];
    }
    d0 = warpSum(d0); d1 = warpSum(d1); m0 = warpSum(m0); m1 = warpSum(m1);
    __shared__ float sh[4][4];
    int w = threadIdx.x >> 5, lane = threadIdx.x & 31;
    if (lane == 0) { sh[w][0] = d0; sh[w][1] = d1; sh[w][2] = m0; sh[w][3] = m1; }
    __syncthreads();
    if (threadIdx.x == 0) {
        float v0 = 0, v1 = 0, v2 = 0, v3 = 0;
        for (int k = 0; k < 4; k++) { v0 += sh[k][0]; v1 += sh[k][1]; v2 += sh[k][2]; v3 += sh[k][3]; }
        g_deg0[0][r] = v0; g_deg0[1][r] = v1; g_rM[0][r] = v2; g_rM[1][r] = v3;
    }
}

// ---- kernel 5: t1[i] = Sum HA[i,k]*rM[k]; scale = d1*d0 -------------------
__global__ void k_scale() {
    int r = blockIdx.x;
    int cnt = min(g_cnt[r], CAP);
    float t0 = 0, t1 = 0;
    for (int t = threadIdx.x; t < cnt; t += blockDim.x) {
        int p = r * CAP + t;
        int col = g_cols[p];
        t0 += g_hav[0][p] * g_rM[0][col];
        t1 += g_hav[1][p] * g_rM[1][col];
    }
    t0 = warpSum(t0); t1 = warpSum(t1);
    __shared__ float sh[4][2];
    int w = threadIdx.x >> 5, lane = threadIdx.x & 31;
    if (lane == 0) { sh[w][0] = t0; sh[w][1] = t1; }
    __syncthreads();
    if (threadIdx.x == 0) {
        float tt[2] = {0.f, 0.f};
        for (int k = 0; k < 4; k++) { tt[0] += sh[k][0]; tt[1] += sh[k][1]; }
        #pragma unroll
        for (int c = 0; c < NC; c++) {
            float dg0 = g_deg0[c][r];
            float d0 = (dg0 > 0.f) ? (1.f / sqrtf(dg0)) : 0.f;
            float dg1 = d0 * tt[c];
            float d1 = (dg1 > 0.f) ? (1.f / sqrtf(dg1)) : 0.f;
            g_scale[c][r] = d0 * d1;
        }
    }
}

// ---------- kernel 6: M = HB @ HB2 (sparse x sparse -> dense rows) ---------
__global__ void k_M() {
    int k = blockIdx.x, c = blockIdx.y;
    __shared__ float acc[NN];
    for (int j = threadIdx.x; j < NN; j += blockDim.x) acc[j] = 0.f;
    __syncthreads();
    int cnt = min(g_cnt[k], CAP);
    int warp = threadIdx.x >> 5, lane = threadIdx.x & 31;
    for (int pi = warp; pi < cnt; pi += 8) {
        int p = k * CAP + pi;
        int l = g_cols[p];
        float hb = g_hbv[c][p];
        int cl = min(g_cnt[l], CAP);
        for (int qi = lane; qi < cl; qi += 32) {
            int q = l * CAP + qi;
            atomicAdd(&acc[g_cols[q]], hb * g_hb2v[c][q]);
        }
    }
    __syncthreads();
    for (int j = threadIdx.x; j < NN; j += blockDim.x)
        g_M[c][k][j] = acc[j];
}

// ---------- kernel 7: H = diag(scale) * HA @ M  (sparse x dense) -----------
__global__ void k_spmm(float* __restrict__ H) {
    int c = blockIdx.z, i = blockIdx.y;
    int j = blockIdx.x * blockDim.x + threadIdx.x;
    __shared__ int   scol[CAP];
    __shared__ float sw[CAP];
    int cnt = min(g_cnt[i], CAP);
    if (threadIdx.x < cnt) {
        int p = i * CAP + threadIdx.x;
        scol[threadIdx.x] = g_cols[p];
        sw[threadIdx.x]   = g_hav[c][p];
    }
    __syncthreads();
    float acc = 0.f;
    int l = 0;
    for (; l + 4 <= cnt; l += 4) {
        float m0 = g_M[c][scol[l + 0]][j];
        float m1 = g_M[c][scol[l + 1]][j];
        float m2 = g_M[c][scol[l + 2]][j];
        float m3 = g_M[c][scol[l + 3]][j];
        acc += sw[l + 0] * m0 + sw[l + 1] * m1 + sw[l + 2] * m2 + sw[l + 3] * m3;
    }
    for (; l < cnt; l++) acc += sw[l] * g_M[c][scol[l]][j];
    H[(size_t)c * NN * NN + (size_t)i * NN + j] = g_scale[c][i] * acc;
}

// -------------------- kernel 8: transpose gcn_w ----------------------------
__global__ void k_transpose(const float* __restrict__ gw) {
    int idx = blockIdx.x * blockDim.x + threadIdx.x;
    if (idx < WOUT * XD) {
        int jj = idx / XD, kk = idx % XD;
        g_gwT[kk][jj] = gw[idx];
    }
}

// -------------------- kernel 9: classification head ------------------------
__global__ void k_head(const float* __restrict__ Xm, const float* __restrict__ gcn_b,
                       const float* __restrict__ lin_w, const float* __restrict__ lin_b,
                       const int* __restrict__ tx, float* __restrict__ y) {
    int t = blockIdx.x;
    int row = tx[t];
    __shared__ float xr[XD];
    __shared__ float h[WOUT];
    for (int k = threadIdx.x; k < XD; k += blockDim.x)
        xr[k] = Xm[(size_t)row * XD + k];
    __syncthreads();
    int j = threadIdx.x;  // 128 threads == WOUT
    float acc = gcn_b[j];
    #pragma unroll 8
    for (int k = 0; k < XD; k++) acc += g_gwT[k][j] * xr[k];
    h[j] = fmaxf(acc, 0.f);
    __syncthreads();
    if (j < NCLS) {
        float acc2 = lin_b[j];
        #pragma unroll 4
        for (int m = 0; m < WOUT; m++)
            acc2 += (lin_w[j * (NC * WOUT) + m] + lin_w[j * (NC * WOUT) + WOUT + m]) * h[m];
        y[t * NCLS + j] = acc2;
    }
}

// ------------------------------ launch -------------------------------------
extern "C" void kernel_launch(void* const* d_in, const int* in_sizes, int n_in,
                              void* d_out, int out_size) {
    const float* A     = (const float*)d_in[0];
    const float* X     = (const float*)d_in[1];
    const float* w01   = (const float*)d_in[2];
    const float* w02   = (const float*)d_in[3];
    const float* w11   = (const float*)d_in[4];
    const float* gcn_w = (const float*)d_in[5];
    const float* gcn_b = (const float*)d_in[6];
    const float* lin_w = (const float*)d_in[7];
    const float* lin_b = (const float*)d_in[8];
    const int*   tx    = (const int*)d_in[9];
    float* out = (float*)d_out;

    k_init<<<1, 256>>>(w01, w02, w11, out + WS_OFF);
    k_fill<<<NN, 256>>>(A);
    k_rowstats<<<NN, 128>>>();
    k_deg<<<NN, 128>>>();
    k_scale<<<NN, 128>>>();
    k_M<<<dim3(NN, NC), 256>>>();
    k_spmm<<<dim3(NN / 256, NN, NC), 256>>>(out + H_OFF);
    k_transpose<<<(WOUT * XD + 255) / 256, 256>>>(gcn_w);
    k_head<<<NT, 128>>>(X, gcn_b, lin_w, lin_b, tx, out + Y_OFF);
}

// round 3
// speedup vs baseline: 1.3348x; 1.3348x over previous
#include <cuda_runtime.h>
#include <cuda_fp16.h>
#include <math.h>

// ---------------------------------------------------------------------------
// GTN: H = diag(d1*d0) * HA * (HB * HB2)  with shared union sparsity pattern.
// M = HB@HB2 stored dense in FP16 (halves L2 traffic of the dominant SpMM).
// Inputs (metadata order):
//  0 A      [5,2048,2048] f32
//  1 X      [2048,512]    f32
//  2 w0_1   [2,5]  3 w0_2 [2,5]  4 w1_1 [2,5]
//  5 gcn_w  [128,512]  6 gcn_b [128]  7 lin_w [8,256]  8 lin_b [8]
//  9 target_x [512] i32
// Output: y[512*8] | all_Ws[3*2*5] | H[2*2048*2048]
// ---------------------------------------------------------------------------

#define NN    2048
#define NE    5
#define NC    2
#define CAP   256
#define NT    512
#define XD    512
#define WOUT  128
#define NCLS  8

#define Y_OFF  0
#define WS_OFF (NT * NCLS)            // 4096
#define H_OFF  (WS_OFF + 3 * NC * NE) // 4126  (8B-aligned in floats, not 16B)

// ------------------------- static device scratch ---------------------------
__device__ int    g_cnt[NN];
__device__ int    g_cols[NN * CAP];
__device__ float  g_hav [NC][NN * CAP];
__device__ float  g_hbv [NC][NN * CAP];
__device__ float  g_hb2v[NC][NN * CAP];
__device__ float  g_s[3][NC][NE];
__device__ float  g_rB  [NC][NN];
__device__ float  g_rB2 [NC][NN];
__device__ float  g_rM  [NC][NN];
__device__ float  g_deg0[NC][NN];
__device__ float  g_scale[NC][NN];
__device__ __align__(16) __half g_Mh[NC][NN][NN];   // 16.8 MB, L2-resident
__device__ float  g_gwT[XD][WOUT];

// ------------------------------ helpers ------------------------------------
__device__ __forceinline__ float warpSum(float v) {
    #pragma unroll
    for (int o = 16; o > 0; o >>= 1) v += __shfl_down_sync(0xffffffffu, v, o);
    return v;
}

// --------------------------- kernel 1: init --------------------------------
__global__ void k_init(const float* __restrict__ w1, const float* __restrict__ w2,
                       const float* __restrict__ w3, float* __restrict__ out_ws) {
    int tid = threadIdx.x;
    for (int i = tid; i < NN; i += blockDim.x) g_cnt[i] = 0;
    if (tid < 3 * NC) {
        int m = tid / NC, c = tid % NC;
        const float* w = (m == 0 ? w1 : (m == 1 ? w2 : w3)) + c * NE;
        float mx = w[0];
        #pragma unroll
        for (int e = 1; e < NE; e++) mx = fmaxf(mx, w[e]);
        float ex[NE], s = 0.f;
        #pragma unroll
        for (int e = 0; e < NE; e++) { ex[e] = expf(w[e] - mx); s += ex[e]; }
        float inv = 1.f / s;
        #pragma unroll
        for (int e = 0; e < NE; e++) {
            float v = ex[e] * inv;
            g_s[m][c][e] = v;
            out_ws[m * NC * NE + c * NE + e] = v;
        }
    }
}

// ------------------- kernel 2: build sparse pattern + values ---------------
__global__ void k_fill(const float* __restrict__ A) {
    int i = blockIdx.x;
    float s1[NC][NE], s2[NC][NE], s3[NC][NE];
    #pragma unroll
    for (int c = 0; c < NC; c++)
        #pragma unroll
        for (int e = 0; e < NE; e++) {
            s1[c][e] = g_s[0][c][e]; s2[c][e] = g_s[1][c][e]; s3[c][e] = g_s[2][c][e];
        }
    for (int j = threadIdx.x; j < NN; j += blockDim.x) {
        float a[NE];
        bool nz = false;
        #pragma unroll
        for (int e = 0; e < NE; e++) {
            a[e] = A[(size_t)e * NN * NN + (size_t)i * NN + j];
            nz |= (a[e] != 0.f);
        }
        if (nz) {
            int slot = atomicAdd(&g_cnt[i], 1);
            if (slot < CAP) {
                int p = i * CAP + slot;
                g_cols[p] = j;
                #pragma unroll
                for (int c = 0; c < NC; c++) {
                    float va = 0.f, vb = 0.f, vb2 = 0.f;
                    #pragma unroll
                    for (int e = 0; e < NE; e++) {
                        va  += s1[c][e] * a[e];
                        vb  += s2[c][e] * a[e];
                        vb2 += s3[c][e] * a[e];
                    }
                    g_hav[c][p] = va; g_hbv[c][p] = vb; g_hb2v[c][p] = vb2;
                }
            }
        }
    }
}

// --------------- kernel 3: row sums of HB, HB2 (per channel) ---------------
__global__ void k_rowstats() {
    int r = blockIdx.x;
    int cnt = min(g_cnt[r], CAP);
    float a0 = 0, a1 = 0, b0 = 0, b1 = 0;
    for (int t = threadIdx.x; t < cnt; t += blockDim.x) {
        int p = r * CAP + t;
        a0 += g_hbv[0][p];  a1 += g_hbv[1][p];
        b0 += g_hb2v[0][p]; b1 += g_hb2v[1][p];
    }
    a0 = warpSum(a0); a1 = warpSum(a1); b0 = warpSum(b0); b1 = warpSum(b1);
    __shared__ float sh[4][4];
    int w = threadIdx.x >> 5, lane = threadIdx.x & 31;
    if (lane == 0) { sh[w][0] = a0; sh[w][1] = a1; sh[w][2] = b0; sh[w][3] = b1; }
    __syncthreads();
    if (threadIdx.x == 0) {
        float v0 = 0, v1 = 0, v2 = 0, v3 = 0;
        for (int k = 0; k < 4; k++) { v0 += sh[k][0]; v1 += sh[k][1]; v2 += sh[k][2]; v3 += sh[k][3]; }
        g_rB[0][r] = v0; g_rB[1][r] = v1; g_rB2[0][r] = v2; g_rB2[1][r] = v3;
    }
}

// ---- kernel 4: deg0[i] = Sum HA[i,k]*rB[k];  rM[i] = Sum HB[i,k]*rB2[k] ----
__global__ void k_deg() {
    int r = blockIdx.x;
    int cnt = min(g_cnt[r], CAP);
    float d0 = 0, d1 = 0, m0 = 0, m1 = 0;
    for (int t = threadIdx.x; t < cnt; t += blockDim.x) {
        int p = r * CAP + t;
        int col = g_cols[p];
        d0 += g_hav[0][p] * g_rB[0][col];
        d1 += g_hav[1][p] * g_rB[1][col];
        m0 += g_hbv[0][p] * g_rB2[0][col];
        m1 += g_hbv[1][p] * g_rB2[1][col];
    }
    d0 = warpSum(d0); d1 = warpSum(d1); m0 = warpSum(m0); m1 = warpSum(m1);
    __shared__ float sh[4][4];
    int w = threadIdx.x >> 5, lane = threadIdx.x & 31;
    if (lane == 0) { sh[w][0] = d0; sh[w][1] = d1; sh[w][2] = m0; sh[w][3] = m1; }
    __syncthreads();
    if (threadIdx.x == 0) {
        float v0 = 0, v1 = 0, v2 = 0, v3 = 0;
        for (int k = 0; k < 4; k++) { v0 += sh[k][0]; v1 += sh[k][1]; v2 += sh[k][2]; v3 += sh[k][3]; }
        g_deg0[0][r] = v0; g_deg0[1][r] = v1; g_rM[0][r] = v2; g_rM[1][r] = v3;
    }
}

// ---- kernel 5: t1[i] = Sum HA[i,k]*rM[k]; scale = d1*d0 -------------------
__global__ void k_scale() {
    int r = blockIdx.x;
    int cnt = min(g_cnt[r], CAP);
    float t0 = 0, t1 = 0;
    for (int t = threadIdx.x; t < cnt; t += blockDim.x) {
        int p = r * CAP + t;
        int col = g_cols[p];
        t0 += g_hav[0][p] * g_rM[0][col];
        t1 += g_hav[1][p] * g_rM[1][col];
    }
    t0 = warpSum(t0); t1 = warpSum(t1);
    __shared__ float sh[4][2];
    int w = threadIdx.x >> 5, lane = threadIdx.x & 31;
    if (lane == 0) { sh[w][0] = t0; sh[w][1] = t1; }
    __syncthreads();
    if (threadIdx.x == 0) {
        float tt[2] = {0.f, 0.f};
        for (int k = 0; k < 4; k++) { tt[0] += sh[k][0]; tt[1] += sh[k][1]; }
        #pragma unroll
        for (int c = 0; c < NC; c++) {
            float dg0 = g_deg0[c][r];
            float d0 = (dg0 > 0.f) ? (1.f / sqrtf(dg0)) : 0.f;
            float dg1 = d0 * tt[c];
            float d1 = (dg1 > 0.f) ? (1.f / sqrtf(dg1)) : 0.f;
            g_scale[c][r] = d0 * d1;
        }
    }
}

// ---------- kernel 6: M = HB @ HB2 (sparse x sparse -> dense fp16) ---------
__global__ void k_M() {
    int k = blockIdx.x, c = blockIdx.y;
    __shared__ float acc[NN];
    for (int j = threadIdx.x; j < NN; j += blockDim.x) acc[j] = 0.f;
    __syncthreads();
    int cnt = min(g_cnt[k], CAP);
    int warp = threadIdx.x >> 5, lane = threadIdx.x & 31;
    for (int pi = warp; pi < cnt; pi += 8) {
        int p = k * CAP + pi;
        int l = g_cols[p];
        float hb = g_hbv[c][p];
        int cl = min(g_cnt[l], CAP);
        for (int qi = lane; qi < cl; qi += 32) {
            int q = l * CAP + qi;
            atomicAdd(&acc[g_cols[q]], hb * g_hb2v[c][q]);
        }
    }
    __syncthreads();
    // write as half2 pairs (coalesced 4B per thread)
    __half2* mrow = reinterpret_cast<__half2*>(&g_Mh[c][k][0]);
    for (int j2 = threadIdx.x; j2 < NN / 2; j2 += blockDim.x)
        mrow[j2] = __floats2half2_rn(acc[2 * j2], acc[2 * j2 + 1]);
}

// ---------- kernel 7: H = diag(scale) * HA @ M  (sparse x dense fp16) ------
// 4 columns per thread: one LDG.64 (uint2 = 4 halves) per nnz per thread.
__global__ void k_spmm(float* __restrict__ H) {
    int c = blockIdx.z, i = blockIdx.y;
    int j0 = (blockIdx.x * blockDim.x + threadIdx.x) * 4;
    __shared__ int   scol[CAP];
    __shared__ float sw[CAP];
    int cnt = min(g_cnt[i], CAP);
    if (threadIdx.x < cnt) {
        int p = i * CAP + threadIdx.x;
        scol[threadIdx.x] = g_cols[p];
        sw[threadIdx.x]   = g_hav[c][p];
    }
    __syncthreads();
    float a0 = 0.f, a1 = 0.f, a2 = 0.f, a3 = 0.f;
    #pragma unroll 4
    for (int l = 0; l < cnt; l++) {
        int k = scol[l];
        float v = sw[l];
        uint2 m = *reinterpret_cast<const uint2*>(&g_Mh[c][k][j0]);
        __half2 h01 = *reinterpret_cast<const __half2*>(&m.x);
        __half2 h23 = *reinterpret_cast<const __half2*>(&m.y);
        float2 f01 = __half22float2(h01);
        float2 f23 = __half22float2(h23);
        a0 += v * f01.x; a1 += v * f01.y;
        a2 += v * f23.x; a3 += v * f23.y;
    }
    float s = g_scale[c][i];
    float* hp = &H[(size_t)c * NN * NN + (size_t)i * NN + j0];
    float2 o01 = make_float2(s * a0, s * a1);
    float2 o23 = make_float2(s * a2, s * a3);
    reinterpret_cast<float2*>(hp)[0] = o01;
    reinterpret_cast<float2*>(hp)[1] = o23;
}

// -------------------- kernel 8: transpose gcn_w ----------------------------
__global__ void k_transpose(const float* __restrict__ gw) {
    int idx = blockIdx.x * blockDim.x + threadIdx.x;
    if (idx < WOUT * XD) {
        int jj = idx / XD, kk = idx % XD;
        g_gwT[kk][jj] = gw[idx];
    }
}

// -------------------- kernel 9: classification head ------------------------
__global__ void k_head(const float* __restrict__ Xm, const float* __restrict__ gcn_b,
                       const float* __restrict__ lin_w, const float* __restrict__ lin_b,
                       const int* __restrict__ tx, float* __restrict__ y) {
    int t = blockIdx.x;
    int row = tx[t];
    __shared__ float xr[XD];
    __shared__ float h[WOUT];
    for (int k = threadIdx.x; k < XD; k += blockDim.x)
        xr[k] = Xm[(size_t)row * XD + k];
    __syncthreads();
    int j = threadIdx.x;  // 128 threads == WOUT
    float acc = gcn_b[j];
    #pragma unroll 8
    for (int k = 0; k < XD; k++) acc += g_gwT[k][j] * xr[k];
    h[j] = fmaxf(acc, 0.f);
    __syncthreads();
    if (j < NCLS) {
        float acc2 = lin_b[j];
        #pragma unroll 4
        for (int m = 0; m < WOUT; m++)
            acc2 += (lin_w[j * (NC * WOUT) + m] + lin_w[j * (NC * WOUT) + WOUT + m]) * h[m];
        y[t * NCLS + j] = acc2;
    }
}

// ------------------------------ launch -------------------------------------
extern "C" void kernel_launch(void* const* d_in, const int* in_sizes, int n_in,
                              void* d_out, int out_size) {
    const float* A     = (const float*)d_in[0];
    const float* X     = (const float*)d_in[1];
    const float* w01   = (const float*)d_in[2];
    const float* w02   = (const float*)d_in[3];
    const float* w11   = (const float*)d_in[4];
    const float* gcn_w = (const float*)d_in[5];
    const float* gcn_b = (const float*)d_in[6];
    const float* lin_w = (const float*)d_in[7];
    const float* lin_b = (const float*)d_in[8];
    const int*   tx    = (const int*)d_in[9];
    float* out = (float*)d_out;

    k_init<<<1, 256>>>(w01, w02, w11, out + WS_OFF);
    k_fill<<<NN, 256>>>(A);
    k_rowstats<<<NN, 128>>>();
    k_deg<<<NN, 128>>>();
    k_scale<<<NN, 128>>>();
    k_M<<<dim3(NN, NC), 256>>>();
    k_spmm<<<dim3(NN / 1024, NN, NC), 256>>>(out + H_OFF);
    k_transpose<<<(WOUT * XD + 255) / 256, 256>>>(gcn_w);
    k_head<<<NT, 128>>>(X, gcn_b, lin_w, lin_b, tx, out + Y_OFF);
}